// round 1
// baseline (speedup 1.0000x reference)
#include <cuda_runtime.h>
#include <cuda_fp16.h>

#define DM   2048
#define HID  5461
#define HPAD 5504
#define MTOT 16384

// ---------------- scratch (device globals; no allocations) ----------------
__device__ __align__(256) __half g_xh [(size_t)MTOT * DM];   // x in fp16
__device__ __align__(256) __half g_w1q[(size_t)HPAD * DM];   // ternary {-1,0,1} fp16, rows>=HID zero
__device__ __align__(256) __half g_w3q[(size_t)HPAD * DM];
__device__ __align__(256) __half g_w2q[(size_t)DM * HPAD];   // [d][h] padded cols zero
__device__ __align__(256) __half g_act[(size_t)MTOT * HPAD]; // gated activation fp16
__device__ float g_partial[1024];
__device__ float g_scale[3];                                  // s1, s3, s2

// ---------------- prologue kernels ----------------
__global__ void reduce_abs_k(const float* __restrict__ w, int n) {
    __shared__ float sd[256];
    float s = 0.f;
    for (int i = blockIdx.x * blockDim.x + threadIdx.x; i < n; i += gridDim.x * blockDim.x)
        s += fabsf(w[i]);
    sd[threadIdx.x] = s; __syncthreads();
    for (int st = 128; st > 0; st >>= 1) {
        if (threadIdx.x < st) sd[threadIdx.x] += sd[threadIdx.x + st];
        __syncthreads();
    }
    if (threadIdx.x == 0) g_partial[blockIdx.x] = sd[0];
}

__global__ void finalize_k(int n, int idx) {
    __shared__ float sd[1024];
    sd[threadIdx.x] = g_partial[threadIdx.x]; __syncthreads();
    for (int st = 512; st > 0; st >>= 1) {
        if (threadIdx.x < st) sd[threadIdx.x] += sd[threadIdx.x + st];
        __syncthreads();
    }
    if (threadIdx.x == 0) g_scale[idx] = sd[0] / (float)n;
}

__global__ void quant_w13_k(const float* __restrict__ w, int sidx) {
    __half* q = (sidx == 0) ? g_w1q : g_w3q;
    int i = blockIdx.x * blockDim.x + threadIdx.x;
    if (i >= HPAD * DM) return;
    int r = i / DM;
    float v = 0.f;
    if (r < HID) {
        float s = g_scale[sidx];
        float t = rintf(w[i] / s);               // round-half-even, matches jnp.round
        v = fmaxf(-1.f, fminf(1.f, t));
    }
    q[i] = __float2half_rn(v);
}

__global__ void quant_w2_k(const float* __restrict__ w) {
    int i = blockIdx.x * blockDim.x + threadIdx.x;
    if (i >= DM * HPAD) return;
    int d = i / HPAD, h = i - d * HPAD;
    float v = 0.f;
    if (h < HID) {
        float s = g_scale[2];
        float t = rintf(w[(size_t)d * HID + h] / s);
        v = fmaxf(-1.f, fminf(1.f, t));
    }
    g_w2q[i] = __float2half_rn(v);
}

__global__ void conv_x_k(const float* __restrict__ x) {
    int i = blockIdx.x * blockDim.x + threadIdx.x;
    const int n4 = MTOT * DM / 4;
    if (i >= n4) return;
    float4 v = ((const float4*)x)[i];
    ((__half2*)g_xh)[2 * i]     = __floats2half2_rn(v.x, v.y);
    ((__half2*)g_xh)[2 * i + 1] = __floats2half2_rn(v.z, v.w);
}

// ---------------- GEMM building blocks ----------------
#define CP_ASYNC16(s, g) asm volatile("cp.async.cg.shared.global [%0], [%1], 16;\n" :: "r"(s), "l"(g))
#define CP_COMMIT()      asm volatile("cp.async.commit_group;\n" ::)
#define CP_WAIT(N)       asm volatile("cp.async.wait_group %0;\n" :: "n"(N))

__device__ __forceinline__ unsigned sptr(const void* p) {
    return (unsigned)__cvta_generic_to_shared(p);
}

__device__ __forceinline__ void ldsm4(unsigned& r0, unsigned& r1, unsigned& r2, unsigned& r3, unsigned a) {
    asm volatile("ldmatrix.sync.aligned.m8n8.x4.shared.b16 {%0,%1,%2,%3}, [%4];\n"
                 : "=r"(r0), "=r"(r1), "=r"(r2), "=r"(r3) : "r"(a));
}

__device__ __forceinline__ void mma16816(float* c, const unsigned* a, unsigned b0, unsigned b1) {
    asm volatile(
        "mma.sync.aligned.m16n8k16.row.col.f32.f16.f16.f32 "
        "{%0,%1,%2,%3},{%4,%5,%6,%7},{%8,%9},{%0,%1,%2,%3};\n"
        : "+f"(c[0]), "+f"(c[1]), "+f"(c[2]), "+f"(c[3])
        : "r"(a[0]), "r"(a[1]), "r"(a[2]), "r"(a[3]), "r"(b0), "r"(b1));
}

// XOR-swizzled smem layout: row of 32 halves (64B), chunk (16B) permuted so
// ldmatrix over any 8 consecutive rows is bank-conflict free. Offsets in halves.
__device__ __forceinline__ int swz(int row, int ch) {
    return (row << 5) + (((ch ^ (row >> 1)) & 3) << 3);
}

__device__ __forceinline__ float siluf(float x) { return x / (1.f + __expf(-x)); }

// One BK=32 stage of MMAs, dual-B (w1 and w3 share the A fragments).
__device__ __forceinline__ void mma_stage_dual(
    const __half* As, const __half* B1s, const __half* B3s,
    int lane, int wm, int wn, float acc1[4][4][4], float acc3[4][4][4])
{
#pragma unroll
    for (int kk = 0; kk < 2; kk++) {
        unsigned a[4][4];
#pragma unroll
        for (int mi = 0; mi < 4; mi++) {
            int row = (wm << 6) + (mi << 4) + (lane & 15);
            int ch  = (kk << 1) + (lane >> 4);
            ldsm4(a[mi][0], a[mi][1], a[mi][2], a[mi][3], sptr(As + swz(row, ch)));
        }
        unsigned b1[2][4], b3[2][4];
#pragma unroll
        for (int gi = 0; gi < 2; gi++) {
            int mat = lane >> 3;
            int row = (wn << 5) + (gi << 4) + ((mat >> 1) << 3) + (lane & 7);
            int ch  = (kk << 1) + (mat & 1);
            ldsm4(b1[gi][0], b1[gi][1], b1[gi][2], b1[gi][3], sptr(B1s + swz(row, ch)));
            ldsm4(b3[gi][0], b3[gi][1], b3[gi][2], b3[gi][3], sptr(B3s + swz(row, ch)));
        }
#pragma unroll
        for (int mi = 0; mi < 4; mi++) {
#pragma unroll
            for (int ni = 0; ni < 4; ni++) {
                int gi = ni >> 1, p = (ni & 1) << 1;
                mma16816(acc1[mi][ni], a[mi], b1[gi][p], b1[gi][p + 1]);
                mma16816(acc3[mi][ni], a[mi], b3[gi][p], b3[gi][p + 1]);
            }
        }
    }
}

__device__ __forceinline__ void mma_stage_single(
    const __half* As, const __half* Bs,
    int lane, int wm, int wn, float acc[4][4][4])
{
#pragma unroll
    for (int kk = 0; kk < 2; kk++) {
        unsigned a[4][4];
#pragma unroll
        for (int mi = 0; mi < 4; mi++) {
            int row = (wm << 6) + (mi << 4) + (lane & 15);
            int ch  = (kk << 1) + (lane >> 4);
            ldsm4(a[mi][0], a[mi][1], a[mi][2], a[mi][3], sptr(As + swz(row, ch)));
        }
        unsigned b[2][4];
#pragma unroll
        for (int gi = 0; gi < 2; gi++) {
            int mat = lane >> 3;
            int row = (wn << 5) + (gi << 4) + ((mat >> 1) << 3) + (lane & 7);
            int ch  = (kk << 1) + (mat & 1);
            ldsm4(b[gi][0], b[gi][1], b[gi][2], b[gi][3], sptr(Bs + swz(row, ch)));
        }
#pragma unroll
        for (int mi = 0; mi < 4; mi++) {
#pragma unroll
            for (int ni = 0; ni < 4; ni++) {
                int gi = ni >> 1, p = (ni & 1) << 1;
                mma16816(acc[mi][ni], a[mi], b[gi][p], b[gi][p + 1]);
            }
        }
    }
}

// ---------------- GEMM1 (fused h1/h3 + SiLU gate), C tile 128x128, K=2048 ----------------
__global__ __launch_bounds__(256, 1) void gemm1_k() {
    __shared__ __align__(16) __half sm[6 * 4096];  // A[2], B1[2], B3[2] stages, 48KB

    const int tid = threadIdx.x, lane = tid & 31, w = tid >> 5;
    const int wm = w >> 2, wn = w & 3;
    const int bm = blockIdx.y, bn = blockIdx.x;

    const __half* gA  = g_xh  + (size_t)bm * 128 * DM;
    const __half* gB1 = g_w1q + (size_t)bn * 128 * DM;
    const __half* gB3 = g_w3q + (size_t)bn * 128 * DM;

    const int lrow = tid >> 2;      // 0..63 (two iterations cover 128 rows)
    const int lch  = tid & 3;       // 16B chunk within 64B row

    float acc1[4][4][4], acc3[4][4][4];
#pragma unroll
    for (int i = 0; i < 4; i++)
#pragma unroll
        for (int j = 0; j < 4; j++)
#pragma unroll
            for (int k = 0; k < 4; k++) { acc1[i][j][k] = 0.f; acc3[i][j][k] = 0.f; }

    const int KT = DM / 32;  // 64

    // prologue: stage 0
    {
        const int k0 = 0;
#pragma unroll
        for (int i = 0; i < 2; i++) {
            int row = lrow + (i << 6);
            int so = swz(row, lch);
            size_t go = (size_t)row * DM + k0 + lch * 8;
            CP_ASYNC16(sptr(sm + so),          gA  + go);
            CP_ASYNC16(sptr(sm + 8192 + so),   gB1 + go);
            CP_ASYNC16(sptr(sm + 16384 + so),  gB3 + go);
        }
        CP_COMMIT();
    }

    for (int kt = 0; kt < KT; kt++) {
        if (kt + 1 < KT) {
            const int st = (kt + 1) & 1;
            const int k0 = (kt + 1) * 32;
#pragma unroll
            for (int i = 0; i < 2; i++) {
                int row = lrow + (i << 6);
                int so = st * 4096 + swz(row, lch);
                size_t go = (size_t)row * DM + k0 + lch * 8;
                CP_ASYNC16(sptr(sm + so),         gA  + go);
                CP_ASYNC16(sptr(sm + 8192 + so),  gB1 + go);
                CP_ASYNC16(sptr(sm + 16384 + so), gB3 + go);
            }
            CP_COMMIT();
            CP_WAIT(1);
        } else {
            CP_WAIT(0);
        }
        __syncthreads();
        const int st = kt & 1;
        mma_stage_dual(sm + st * 4096, sm + 8192 + st * 4096, sm + 16384 + st * 4096,
                       lane, wm, wn, acc1, acc3);
        __syncthreads();
    }

    // epilogue: g = silu(s1*h1) * (s3*h3), fp16 store
    const float s1 = g_scale[0], s3v = g_scale[1];
    const int rb = bm * 128 + wm * 64;
    const int cb = bn * 128 + wn * 32;
#pragma unroll
    for (int mi = 0; mi < 4; mi++) {
        int r0 = rb + mi * 16 + (lane >> 2);
#pragma unroll
        for (int ni = 0; ni < 4; ni++) {
            int c = cb + ni * 8 + ((lane & 3) << 1);
            float h10 = s1 * acc1[mi][ni][0], h11 = s1 * acc1[mi][ni][1];
            float h12 = s1 * acc1[mi][ni][2], h13 = s1 * acc1[mi][ni][3];
            float h30 = s3v * acc3[mi][ni][0], h31 = s3v * acc3[mi][ni][1];
            float h32 = s3v * acc3[mi][ni][2], h33 = s3v * acc3[mi][ni][3];
            float g0 = siluf(h10) * h30, g1 = siluf(h11) * h31;
            float g2 = siluf(h12) * h32, g3 = siluf(h13) * h33;
            *(__half2*)(g_act + (size_t)r0 * HPAD + c)       = __floats2half2_rn(g0, g1);
            *(__half2*)(g_act + (size_t)(r0 + 8) * HPAD + c) = __floats2half2_rn(g2, g3);
        }
    }
}

// ---------------- GEMM2: out = s2 * (g · w2q^T), K=HPAD, fp32 out ----------------
__global__ __launch_bounds__(256, 1) void gemm2_k(float* __restrict__ out) {
    __shared__ __align__(16) __half sm[4 * 4096];  // A[2], B[2], 32KB

    const int tid = threadIdx.x, lane = tid & 31, w = tid >> 5;
    const int wm = w >> 2, wn = w & 3;
    const int bm = blockIdx.y, bn = blockIdx.x;

    const __half* gA = g_act + (size_t)bm * 128 * HPAD;
    const __half* gB = g_w2q + (size_t)bn * 128 * HPAD;

    const int lrow = tid >> 2;
    const int lch  = tid & 3;

    float acc[4][4][4];
#pragma unroll
    for (int i = 0; i < 4; i++)
#pragma unroll
        for (int j = 0; j < 4; j++)
#pragma unroll
            for (int k = 0; k < 4; k++) acc[i][j][k] = 0.f;

    const int KT = HPAD / 32;  // 172

    {
#pragma unroll
        for (int i = 0; i < 2; i++) {
            int row = lrow + (i << 6);
            int so = swz(row, lch);
            size_t go = (size_t)row * HPAD + lch * 8;
            CP_ASYNC16(sptr(sm + so),        gA + go);
            CP_ASYNC16(sptr(sm + 8192 + so), gB + go);
        }
        CP_COMMIT();
    }

    for (int kt = 0; kt < KT; kt++) {
        if (kt + 1 < KT) {
            const int st = (kt + 1) & 1;
            const int k0 = (kt + 1) * 32;
#pragma unroll
            for (int i = 0; i < 2; i++) {
                int row = lrow + (i << 6);
                int so = st * 4096 + swz(row, lch);
                size_t go = (size_t)row * HPAD + k0 + lch * 8;
                CP_ASYNC16(sptr(sm + so),        gA + go);
                CP_ASYNC16(sptr(sm + 8192 + so), gB + go);
            }
            CP_COMMIT();
            CP_WAIT(1);
        } else {
            CP_WAIT(0);
        }
        __syncthreads();
        const int st = kt & 1;
        mma_stage_single(sm + st * 4096, sm + 8192 + st * 4096, lane, wm, wn, acc);
        __syncthreads();
    }

    const float s2 = g_scale[2];
    const int rb = bm * 128 + wm * 64;
    const int cb = bn * 128 + wn * 32;
#pragma unroll
    for (int mi = 0; mi < 4; mi++) {
        int r0 = rb + mi * 16 + (lane >> 2);
#pragma unroll
        for (int ni = 0; ni < 4; ni++) {
            int c = cb + ni * 8 + ((lane & 3) << 1);
            float2 v;
            v.x = s2 * acc[mi][ni][0]; v.y = s2 * acc[mi][ni][1];
            *(float2*)(out + (size_t)r0 * DM + c) = v;
            v.x = s2 * acc[mi][ni][2]; v.y = s2 * acc[mi][ni][3];
            *(float2*)(out + (size_t)(r0 + 8) * DM + c) = v;
        }
    }
}

// ---------------- launch ----------------
extern "C" void kernel_launch(void* const* d_in, const int* in_sizes, int n_in,
                              void* d_out, int out_size) {
    const float* x  = (const float*)d_in[0];
    const float* w1 = (const float*)d_in[1];
    const float* w3 = (const float*)d_in[2];
    const float* w2 = (const float*)d_in[3];
    float* out = (float*)d_out;

    const int nw = HID * DM;  // 11,184,128 (same for all three weights)

    // per-tensor scales (deterministic two-pass reduction)
    reduce_abs_k<<<1024, 256>>>(w1, nw);  finalize_k<<<1, 1024>>>(nw, 0);
    reduce_abs_k<<<1024, 256>>>(w3, nw);  finalize_k<<<1, 1024>>>(nw, 1);
    reduce_abs_k<<<1024, 256>>>(w2, nw);  finalize_k<<<1, 1024>>>(nw, 2);

    // ternary-quantize weights into padded fp16 scratch
    quant_w13_k<<<(HPAD * DM + 255) / 256, 256>>>(w1, 0);
    quant_w13_k<<<(HPAD * DM + 255) / 256, 256>>>(w3, 1);
    quant_w2_k <<<(DM * HPAD + 255) / 256, 256>>>(w2);

    // x -> fp16
    conv_x_k<<<(MTOT * DM / 4 + 255) / 256, 256>>>(x);

    // fused GEMM1 (h1 & h3 + SiLU gate) and GEMM2
    gemm1_k<<<dim3(HPAD / 128, MTOT / 128), 256>>>();
    gemm2_k<<<dim3(DM / 128, MTOT / 128), 256>>>(out);
}

// round 3
// speedup vs baseline: 1.1253x; 1.1253x over previous
#include <cuda_runtime.h>
#include <cuda_fp16.h>
#include <cstdint>

#define DM   2048
#define HID  5461
#define HPAD 5504
#define MTOT 16384

// ---------------- scratch (device globals; no allocations) ----------------
__device__ __align__(256) __half g_xh [(size_t)MTOT * DM];   // x in fp16
__device__ __align__(256) __half g_w1q[(size_t)HPAD * DM];   // ternary {-1,0,1} fp16
__device__ __align__(256) __half g_w3q[(size_t)HPAD * DM];
__device__ __align__(256) __half g_w2q[(size_t)DM * HPAD];   // [d][h] padded cols zero
__device__ __align__(256) __half g_act[(size_t)MTOT * HPAD]; // gated activation fp16
__device__ float g_partial[1024];
__device__ float g_scale[3];                                  // s1, s3, s2

// ---------------- prologue kernels ----------------
__global__ void reduce_abs_k(const float* __restrict__ w, int n) {
    __shared__ float sd[256];
    float s = 0.f;
    for (int i = blockIdx.x * blockDim.x + threadIdx.x; i < n; i += gridDim.x * blockDim.x)
        s += fabsf(w[i]);
    sd[threadIdx.x] = s; __syncthreads();
    for (int st = 128; st > 0; st >>= 1) {
        if (threadIdx.x < st) sd[threadIdx.x] += sd[threadIdx.x + st];
        __syncthreads();
    }
    if (threadIdx.x == 0) g_partial[blockIdx.x] = sd[0];
}

__global__ void finalize_k(int n, int idx) {
    __shared__ float sd[1024];
    sd[threadIdx.x] = g_partial[threadIdx.x]; __syncthreads();
    for (int st = 512; st > 0; st >>= 1) {
        if (threadIdx.x < st) sd[threadIdx.x] += sd[threadIdx.x + st];
        __syncthreads();
    }
    if (threadIdx.x == 0) g_scale[idx] = sd[0] / (float)n;
}

__global__ void quant_w13_k(const float* __restrict__ w, int sidx) {
    __half* q = (sidx == 0) ? g_w1q : g_w3q;
    int i = blockIdx.x * blockDim.x + threadIdx.x;
    if (i >= HPAD * DM) return;
    int r = i / DM;
    float v = 0.f;
    if (r < HID) {
        float s = g_scale[sidx];
        float t = rintf(w[i] / s);               // round-half-even, matches jnp.round
        v = fmaxf(-1.f, fminf(1.f, t));
    }
    q[i] = __float2half_rn(v);
}

__global__ void quant_w2_k(const float* __restrict__ w) {
    int i = blockIdx.x * blockDim.x + threadIdx.x;
    if (i >= DM * HPAD) return;
    int d = i / HPAD, h = i - d * HPAD;
    float v = 0.f;
    if (h < HID) {
        float s = g_scale[2];
        float t = rintf(w[(size_t)d * HID + h] / s);
        v = fmaxf(-1.f, fminf(1.f, t));
    }
    g_w2q[i] = __float2half_rn(v);
}

__global__ void conv_x_k(const float* __restrict__ x) {
    int i = blockIdx.x * blockDim.x + threadIdx.x;
    const int n4 = MTOT * DM / 4;
    if (i >= n4) return;
    float4 v = ((const float4*)x)[i];
    ((__half2*)g_xh)[2 * i]     = __floats2half2_rn(v.x, v.y);
    ((__half2*)g_xh)[2 * i + 1] = __floats2half2_rn(v.z, v.w);
}

// ---------------- GEMM building blocks ----------------
#define CP_ASYNC16(s, g) asm volatile("cp.async.cg.shared.global [%0], [%1], 16;\n" :: "r"(s), "l"(g))
#define CP_COMMIT()      asm volatile("cp.async.commit_group;\n" ::)
#define CP_WAIT(N)       asm volatile("cp.async.wait_group %0;\n" :: "n"(N))

__device__ __forceinline__ unsigned sptr(const void* p) {
    return (unsigned)__cvta_generic_to_shared(p);
}

__device__ __forceinline__ void ldsm4(unsigned& r0, unsigned& r1, unsigned& r2, unsigned& r3, unsigned a) {
    asm volatile("ldmatrix.sync.aligned.m8n8.x4.shared.b16 {%0,%1,%2,%3}, [%4];\n"
                 : "=r"(r0), "=r"(r1), "=r"(r2), "=r"(r3) : "r"(a));
}

__device__ __forceinline__ void mma16816(float* c, const unsigned* a, unsigned b0, unsigned b1) {
    asm volatile(
        "mma.sync.aligned.m16n8k16.row.col.f32.f16.f16.f32 "
        "{%0,%1,%2,%3},{%4,%5,%6,%7},{%8,%9},{%0,%1,%2,%3};\n"
        : "+f"(c[0]), "+f"(c[1]), "+f"(c[2]), "+f"(c[3])
        : "r"(a[0]), "r"(a[1]), "r"(a[2]), "r"(a[3]), "r"(b0), "r"(b1));
}

// XOR-swizzled smem: rows of 32 halves (64B), 16B chunk permuted by row.
__device__ __forceinline__ int swz(int row, int ch) {
    return (row << 5) + (((ch ^ (row >> 1)) & 3) << 3);
}

__device__ __forceinline__ float siluf(float x) { return x / (1.f + __expf(-x)); }

// One BK=32 stage of MMAs, dual-B (w1 and w3 share the A fragments).
__device__ __forceinline__ void mma_stage_dual(
    const __half* As, const __half* B1s, const __half* B3s,
    int lane, int wm, int wn, float acc1[4][4][4], float acc3[4][4][4])
{
#pragma unroll
    for (int kk = 0; kk < 2; kk++) {
        unsigned a[4][4];
#pragma unroll
        for (int mi = 0; mi < 4; mi++) {
            int row = (wm << 6) + (mi << 4) + (lane & 15);
            int ch  = (kk << 1) + (lane >> 4);
            ldsm4(a[mi][0], a[mi][1], a[mi][2], a[mi][3], sptr(As + swz(row, ch)));
        }
        unsigned b1[2][4], b3[2][4];
#pragma unroll
        for (int gi = 0; gi < 2; gi++) {
            int mat = lane >> 3;
            int row = (wn << 5) + (gi << 4) + ((mat >> 1) << 3) + (lane & 7);
            int ch  = (kk << 1) + (mat & 1);
            ldsm4(b1[gi][0], b1[gi][1], b1[gi][2], b1[gi][3], sptr(B1s + swz(row, ch)));
            ldsm4(b3[gi][0], b3[gi][1], b3[gi][2], b3[gi][3], sptr(B3s + swz(row, ch)));
        }
#pragma unroll
        for (int mi = 0; mi < 4; mi++) {
#pragma unroll
            for (int ni = 0; ni < 4; ni++) {
                int gi = ni >> 1, p = (ni & 1) << 1;
                mma16816(acc1[mi][ni], a[mi], b1[gi][p], b1[gi][p + 1]);
                mma16816(acc3[mi][ni], a[mi], b3[gi][p], b3[gi][p + 1]);
            }
        }
    }
}

__device__ __forceinline__ void mma_stage_single(
    const __half* As, const __half* Bs,
    int lane, int wm, int wn, float acc[4][4][4])
{
#pragma unroll
    for (int kk = 0; kk < 2; kk++) {
        unsigned a[4][4];
#pragma unroll
        for (int mi = 0; mi < 4; mi++) {
            int row = (wm << 6) + (mi << 4) + (lane & 15);
            int ch  = (kk << 1) + (lane >> 4);
            ldsm4(a[mi][0], a[mi][1], a[mi][2], a[mi][3], sptr(As + swz(row, ch)));
        }
        unsigned b[2][4];
#pragma unroll
        for (int gi = 0; gi < 2; gi++) {
            int mat = lane >> 3;
            int row = (wn << 5) + (gi << 4) + ((mat >> 1) << 3) + (lane & 7);
            int ch  = (kk << 1) + (mat & 1);
            ldsm4(b[gi][0], b[gi][1], b[gi][2], b[gi][3], sptr(Bs + swz(row, ch)));
        }
#pragma unroll
        for (int mi = 0; mi < 4; mi++) {
#pragma unroll
            for (int ni = 0; ni < 4; ni++) {
                int gi = ni >> 1, p = (ni & 1) << 1;
                mma16816(acc[mi][ni], a[mi], b[gi][p], b[gi][p + 1]);
            }
        }
    }
}

// ---------------- GEMM1 (fused h1/h3 + SiLU gate) ----------------
// C tile 128x128, K=2048, BK=32, 4-stage cp.async pipeline (96KB dynamic smem).
#define G1_STG 12288   // halves per stage: A 4096 + B1 4096 + B3 4096
#define G1_SMEM (4 * G1_STG * 2)

__device__ __forceinline__ void g1_load(__half* st, const __half* gA, const __half* gB1,
                                        const __half* gB3, int k0, int lrow, int lch) {
#pragma unroll
    for (int i = 0; i < 2; i++) {
        int row = lrow + (i << 6);
        int so = swz(row, lch);
        size_t go = (size_t)row * DM + k0 + lch * 8;
        CP_ASYNC16(sptr(st + so),        gA  + go);
        CP_ASYNC16(sptr(st + 4096 + so), gB1 + go);
        CP_ASYNC16(sptr(st + 8192 + so), gB3 + go);
    }
}

__global__ __launch_bounds__(256, 1) void gemm1_k() {
    extern __shared__ __align__(16) __half sm1[];

    const int tid = threadIdx.x, lane = tid & 31, w = tid >> 5;
    const int wm = w >> 2, wn = w & 3;
    const int bm = blockIdx.y, bn = blockIdx.x;
    const int lrow = tid >> 2, lch = tid & 3;

    const __half* gA  = g_xh  + (size_t)bm * 128 * DM;
    const __half* gB1 = g_w1q + (size_t)bn * 128 * DM;
    const __half* gB3 = g_w3q + (size_t)bn * 128 * DM;

    float acc1[4][4][4], acc3[4][4][4];
#pragma unroll
    for (int i = 0; i < 4; i++)
#pragma unroll
        for (int j = 0; j < 4; j++)
#pragma unroll
            for (int k = 0; k < 4; k++) { acc1[i][j][k] = 0.f; acc3[i][j][k] = 0.f; }

    const int KT = DM / 32;  // 64

    // prologue: fill stages 0..2
#pragma unroll
    for (int s = 0; s < 3; s++) {
        g1_load(sm1 + s * G1_STG, gA, gB1, gB3, s * 32, lrow, lch);
        CP_COMMIT();
    }

    for (int kt = 0; kt < KT; kt++) {
        CP_WAIT(2);
        __syncthreads();
        const int nx = kt + 3;
        if (nx < KT)
            g1_load(sm1 + (nx & 3) * G1_STG, gA, gB1, gB3, nx * 32, lrow, lch);
        CP_COMMIT();
        const __half* stb = sm1 + (kt & 3) * G1_STG;
        mma_stage_dual(stb, stb + 4096, stb + 8192, lane, wm, wn, acc1, acc3);
    }

    // epilogue: g = silu(s1*h1) * (s3*h3), fp16 store
    const float s1 = g_scale[0], s3v = g_scale[1];
    const int rb = bm * 128 + wm * 64;
    const int cb = bn * 128 + wn * 32;
#pragma unroll
    for (int mi = 0; mi < 4; mi++) {
        int r0 = rb + mi * 16 + (lane >> 2);
#pragma unroll
        for (int ni = 0; ni < 4; ni++) {
            int c = cb + ni * 8 + ((lane & 3) << 1);
            float h10 = s1 * acc1[mi][ni][0], h11 = s1 * acc1[mi][ni][1];
            float h12 = s1 * acc1[mi][ni][2], h13 = s1 * acc1[mi][ni][3];
            float h30 = s3v * acc3[mi][ni][0], h31 = s3v * acc3[mi][ni][1];
            float h32 = s3v * acc3[mi][ni][2], h33 = s3v * acc3[mi][ni][3];
            float g0 = siluf(h10) * h30, g1 = siluf(h11) * h31;
            float g2 = siluf(h12) * h32, g3 = siluf(h13) * h33;
            *(__half2*)(g_act + (size_t)r0 * HPAD + c)       = __floats2half2_rn(g0, g1);
            *(__half2*)(g_act + (size_t)(r0 + 8) * HPAD + c) = __floats2half2_rn(g2, g3);
        }
    }
}

// ---------------- GEMM2: out = s2 * (g . w2q^T) ----------------
// C tile 128x128, K=HPAD, BK=32, 4-stage pipeline (64KB dynamic smem), 2 CTAs/SM.
#define G2_STG 8192    // halves per stage: A 4096 + B 4096
#define G2_SMEM (4 * G2_STG * 2)

__device__ __forceinline__ void g2_load(__half* st, const __half* gA, const __half* gB,
                                        int k0, int lrow, int lch) {
#pragma unroll
    for (int i = 0; i < 2; i++) {
        int row = lrow + (i << 6);
        int so = swz(row, lch);
        size_t go = (size_t)row * HPAD + k0 + lch * 8;
        CP_ASYNC16(sptr(st + so),        gA + go);
        CP_ASYNC16(sptr(st + 4096 + so), gB + go);
    }
}

__global__ __launch_bounds__(256, 2) void gemm2_k(float* __restrict__ out) {
    extern __shared__ __align__(16) __half sm2[];

    const int tid = threadIdx.x, lane = tid & 31, w = tid >> 5;
    const int wm = w >> 2, wn = w & 3;
    const int bm = blockIdx.y, bn = blockIdx.x;
    const int lrow = tid >> 2, lch = tid & 3;

    const __half* gA = g_act + (size_t)bm * 128 * HPAD;
    const __half* gB = g_w2q + (size_t)bn * 128 * HPAD;

    float acc[4][4][4];
#pragma unroll
    for (int i = 0; i < 4; i++)
#pragma unroll
        for (int j = 0; j < 4; j++)
#pragma unroll
            for (int k = 0; k < 4; k++) acc[i][j][k] = 0.f;

    const int KT = HPAD / 32;  // 172

#pragma unroll
    for (int s = 0; s < 3; s++) {
        g2_load(sm2 + s * G2_STG, gA, gB, s * 32, lrow, lch);
        CP_COMMIT();
    }

    for (int kt = 0; kt < KT; kt++) {
        CP_WAIT(2);
        __syncthreads();
        const int nx = kt + 3;
        if (nx < KT)
            g2_load(sm2 + (nx & 3) * G2_STG, gA, gB, nx * 32, lrow, lch);
        CP_COMMIT();
        const __half* stb = sm2 + (kt & 3) * G2_STG;
        mma_stage_single(stb, stb + 4096, lane, wm, wn, acc);
    }

    const float s2 = g_scale[2];
    const int rb = bm * 128 + wm * 64;
    const int cb = bn * 128 + wn * 32;
#pragma unroll
    for (int mi = 0; mi < 4; mi++) {
        int r0 = rb + mi * 16 + (lane >> 2);
#pragma unroll
        for (int ni = 0; ni < 4; ni++) {
            int c = cb + ni * 8 + ((lane & 3) << 1);
            float2 v;
            v.x = s2 * acc[mi][ni][0]; v.y = s2 * acc[mi][ni][1];
            *(float2*)(out + (size_t)r0 * DM + c) = v;
            v.x = s2 * acc[mi][ni][2]; v.y = s2 * acc[mi][ni][3];
            *(float2*)(out + (size_t)(r0 + 8) * DM + c) = v;
        }
    }
}

// ---------------- launch ----------------
extern "C" void kernel_launch(void* const* d_in, const int* in_sizes, int n_in,
                              void* d_out, int out_size) {
    const float* x  = (const float*)d_in[0];
    const float* w1 = (const float*)d_in[1];
    const float* w3 = (const float*)d_in[2];
    const float* w2 = (const float*)d_in[3];
    float* out = (float*)d_out;

    const int nw = HID * DM;  // 11,184,128

    cudaFuncSetAttribute(gemm1_k, cudaFuncAttributeMaxDynamicSharedMemorySize, G1_SMEM);
    cudaFuncSetAttribute(gemm2_k, cudaFuncAttributeMaxDynamicSharedMemorySize, G2_SMEM);

    // per-tensor scales (deterministic two-pass reduction)
    reduce_abs_k<<<1024, 256>>>(w1, nw);  finalize_k<<<1, 1024>>>(nw, 0);
    reduce_abs_k<<<1024, 256>>>(w3, nw);  finalize_k<<<1, 1024>>>(nw, 1);
    reduce_abs_k<<<1024, 256>>>(w2, nw);  finalize_k<<<1, 1024>>>(nw, 2);

    // ternary-quantize weights into padded fp16 scratch
    quant_w13_k<<<(HPAD * DM + 255) / 256, 256>>>(w1, 0);
    quant_w13_k<<<(HPAD * DM + 255) / 256, 256>>>(w3, 1);
    quant_w2_k <<<(DM * HPAD + 255) / 256, 256>>>(w2);

    // x -> fp16
    conv_x_k<<<(MTOT * DM / 4 + 255) / 256, 256>>>(x);

    // GEMMs (multistage cp.async + mma.sync)
    gemm1_k<<<dim3(HPAD / 128, MTOT / 128), 256, G1_SMEM>>>();
    gemm2_k<<<dim3(DM / 128, MTOT / 128), 256, G2_SMEM>>>(out);
}

// round 4
// speedup vs baseline: 1.2120x; 1.0771x over previous
#include <cuda_runtime.h>
#include <cuda_fp16.h>
#include <cstdint>

#define DM   2048
#define HID  5461
#define HPAD 5504
#define MTOT 16384

// ---------------- scratch (device globals; no allocations) ----------------
__device__ __align__(256) __half g_xh [(size_t)MTOT * DM];   // x in fp16
__device__ __align__(256) __half g_w1q[(size_t)HPAD * DM];   // ternary {-1,0,1} fp16
__device__ __align__(256) __half g_w3q[(size_t)HPAD * DM];
__device__ __align__(256) __half g_w2q[(size_t)DM * HPAD];   // [d][h] padded cols zero
__device__ __align__(256) __half g_act[(size_t)MTOT * HPAD]; // gated activation fp16
__device__ float g_partial[3 * 512];
__device__ float g_scale[3];                                  // s1, s3, s2

// ---------------- prologue kernels (fused; 4 launches before GEMMs) ----------------
__global__ void reduce_abs3_k(const float* __restrict__ w1, const float* __restrict__ w3,
                              const float* __restrict__ w2, int n) {
    __shared__ float sd[256];
    const float* w = (blockIdx.y == 0) ? w1 : (blockIdx.y == 1) ? w3 : w2;
    float s = 0.f;
    for (int i = blockIdx.x * blockDim.x + threadIdx.x; i < n; i += gridDim.x * blockDim.x)
        s += fabsf(w[i]);
    sd[threadIdx.x] = s; __syncthreads();
    for (int st = 128; st > 0; st >>= 1) {
        if (threadIdx.x < st) sd[threadIdx.x] += sd[threadIdx.x + st];
        __syncthreads();
    }
    if (threadIdx.x == 0) g_partial[blockIdx.y * 512 + blockIdx.x] = sd[0];
}

__global__ void finalize3_k(int n) {
    __shared__ float sd[512];
    sd[threadIdx.x] = g_partial[blockIdx.x * 512 + threadIdx.x]; __syncthreads();
    for (int st = 256; st > 0; st >>= 1) {
        if (threadIdx.x < st) sd[threadIdx.x] += sd[threadIdx.x + st];
        __syncthreads();
    }
    if (threadIdx.x == 0) g_scale[blockIdx.x] = sd[0] / (float)n;
}

__global__ void quant_w13_k(const float* __restrict__ w1, const float* __restrict__ w3) {
    const float* w = (blockIdx.y == 0) ? w1 : w3;
    __half* q = (blockIdx.y == 0) ? g_w1q : g_w3q;
    float s = g_scale[blockIdx.y];
    int i = blockIdx.x * blockDim.x + threadIdx.x;
    if (i >= HPAD * DM) return;
    int r = i / DM;
    float v = 0.f;
    if (r < HID) {
        float t = rintf(w[i] / s);               // round-half-even, matches jnp.round
        v = fmaxf(-1.f, fminf(1.f, t));
    }
    q[i] = __float2half_rn(v);
}

__global__ void quant_w2_k(const float* __restrict__ w) {
    int i = blockIdx.x * blockDim.x + threadIdx.x;
    if (i >= DM * HPAD) return;
    int d = i / HPAD, h = i - d * HPAD;
    float v = 0.f;
    if (h < HID) {
        float s = g_scale[2];
        float t = rintf(w[(size_t)d * HID + h] / s);
        v = fmaxf(-1.f, fminf(1.f, t));
    }
    g_w2q[i] = __float2half_rn(v);
}

__global__ void conv_x_k(const float* __restrict__ x) {
    int i = blockIdx.x * blockDim.x + threadIdx.x;
    const int n4 = MTOT * DM / 4;
    if (i >= n4) return;
    float4 v = ((const float4*)x)[i];
    ((__half2*)g_xh)[2 * i]     = __floats2half2_rn(v.x, v.y);
    ((__half2*)g_xh)[2 * i + 1] = __floats2half2_rn(v.z, v.w);
}

// ---------------- GEMM building blocks ----------------
#define CP_ASYNC16(s, g) asm volatile("cp.async.cg.shared.global [%0], [%1], 16;\n" :: "r"(s), "l"(g))
#define CP_COMMIT()      asm volatile("cp.async.commit_group;\n" ::)
#define CP_WAIT(N)       asm volatile("cp.async.wait_group %0;\n" :: "n"(N))

__device__ __forceinline__ unsigned sptr(const void* p) {
    return (unsigned)__cvta_generic_to_shared(p);
}

__device__ __forceinline__ void ldsm4(unsigned& r0, unsigned& r1, unsigned& r2, unsigned& r3, unsigned a) {
    asm volatile("ldmatrix.sync.aligned.m8n8.x4.shared.b16 {%0,%1,%2,%3}, [%4];\n"
                 : "=r"(r0), "=r"(r1), "=r"(r2), "=r"(r3) : "r"(a));
}

__device__ __forceinline__ void mma16816(float* c, const unsigned* a, unsigned b0, unsigned b1) {
    asm volatile(
        "mma.sync.aligned.m16n8k16.row.col.f32.f16.f16.f32 "
        "{%0,%1,%2,%3},{%4,%5,%6,%7},{%8,%9},{%0,%1,%2,%3};\n"
        : "+f"(c[0]), "+f"(c[1]), "+f"(c[2]), "+f"(c[3])
        : "r"(a[0]), "r"(a[1]), "r"(a[2]), "r"(a[3]), "r"(b0), "r"(b1));
}

// 128B-row swizzle: row = 64 halves, 8 chunks of 16B, chunk XOR (row&7). Offsets in halves.
__device__ __forceinline__ int swz(int row, int ch) {
    return (row << 6) + (((ch ^ row) & 7) << 3);
}

__device__ __forceinline__ float siluf(float x) { return x / (1.f + __expf(-x)); }

// One BK=64 stage of MMAs, dual-B (w1 and w3 share the A fragments).
__device__ __forceinline__ void mma_stage_dual(
    const __half* As, const __half* B1s, const __half* B3s,
    int lane, int wm, int wn, float acc1[4][4][4], float acc3[4][4][4])
{
#pragma unroll
    for (int kk = 0; kk < 4; kk++) {
        unsigned a[4][4];
#pragma unroll
        for (int mi = 0; mi < 4; mi++) {
            int row = (wm << 6) + (mi << 4) + (lane & 15);
            int ch  = (kk << 1) + (lane >> 4);
            ldsm4(a[mi][0], a[mi][1], a[mi][2], a[mi][3], sptr(As + swz(row, ch)));
        }
        unsigned b1[2][4], b3[2][4];
#pragma unroll
        for (int gi = 0; gi < 2; gi++) {
            int mat = lane >> 3;
            int row = (wn << 5) + (gi << 4) + ((mat >> 1) << 3) + (lane & 7);
            int ch  = (kk << 1) + (mat & 1);
            ldsm4(b1[gi][0], b1[gi][1], b1[gi][2], b1[gi][3], sptr(B1s + swz(row, ch)));
            ldsm4(b3[gi][0], b3[gi][1], b3[gi][2], b3[gi][3], sptr(B3s + swz(row, ch)));
        }
#pragma unroll
        for (int mi = 0; mi < 4; mi++) {
#pragma unroll
            for (int ni = 0; ni < 4; ni++) {
                int gi = ni >> 1, p = (ni & 1) << 1;
                mma16816(acc1[mi][ni], a[mi], b1[gi][p], b1[gi][p + 1]);
                mma16816(acc3[mi][ni], a[mi], b3[gi][p], b3[gi][p + 1]);
            }
        }
    }
}

__device__ __forceinline__ void mma_stage_single(
    const __half* As, const __half* Bs,
    int lane, int wm, int wn, float acc[4][4][4])
{
#pragma unroll
    for (int kk = 0; kk < 4; kk++) {
        unsigned a[4][4];
#pragma unroll
        for (int mi = 0; mi < 4; mi++) {
            int row = (wm << 6) + (mi << 4) + (lane & 15);
            int ch  = (kk << 1) + (lane >> 4);
            ldsm4(a[mi][0], a[mi][1], a[mi][2], a[mi][3], sptr(As + swz(row, ch)));
        }
        unsigned b[2][4];
#pragma unroll
        for (int gi = 0; gi < 2; gi++) {
            int mat = lane >> 3;
            int row = (wn << 5) + (gi << 4) + ((mat >> 1) << 3) + (lane & 7);
            int ch  = (kk << 1) + (mat & 1);
            ldsm4(b[gi][0], b[gi][1], b[gi][2], b[gi][3], sptr(Bs + swz(row, ch)));
        }
#pragma unroll
        for (int mi = 0; mi < 4; mi++) {
#pragma unroll
            for (int ni = 0; ni < 4; ni++) {
                int gi = ni >> 1, p = (ni & 1) << 1;
                mma16816(acc[mi][ni], a[mi], b[gi][p], b[gi][p + 1]);
            }
        }
    }
}

// ---------------- GEMM1 (fused h1/h3 + SiLU gate) ----------------
// C tile 128x128, K=2048, BK=64, 4-stage cp.async pipeline (192KB dynamic smem).
#define G1_STG 24576   // halves per stage: A 8192 + B1 8192 + B3 8192
#define G1_SMEM (4 * G1_STG * 2)

__device__ __forceinline__ void g1_load(__half* st, const __half* gA, const __half* gB1,
                                        const __half* gB3, int k0, int lrow, int lch) {
#pragma unroll
    for (int i = 0; i < 4; i++) {
        int row = lrow + (i << 5);
        int so = swz(row, lch);
        size_t go = (size_t)row * DM + k0 + lch * 8;
        CP_ASYNC16(sptr(st + so),         gA  + go);
        CP_ASYNC16(sptr(st + 8192 + so),  gB1 + go);
        CP_ASYNC16(sptr(st + 16384 + so), gB3 + go);
    }
}

__global__ __launch_bounds__(256, 1) void gemm1_k() {
    extern __shared__ __align__(16) __half sm1[];

    const int tid = threadIdx.x, lane = tid & 31, w = tid >> 5;
    const int wm = w >> 2, wn = w & 3;
    const int bm = blockIdx.y, bn = blockIdx.x;
    const int lrow = tid >> 3, lch = tid & 7;   // 32 rows per pass, 8 chunks/row

    const __half* gA  = g_xh  + (size_t)bm * 128 * DM;
    const __half* gB1 = g_w1q + (size_t)bn * 128 * DM;
    const __half* gB3 = g_w3q + (size_t)bn * 128 * DM;

    float acc1[4][4][4], acc3[4][4][4];
#pragma unroll
    for (int i = 0; i < 4; i++)
#pragma unroll
        for (int j = 0; j < 4; j++)
#pragma unroll
            for (int k = 0; k < 4; k++) { acc1[i][j][k] = 0.f; acc3[i][j][k] = 0.f; }

    const int KT = DM / 64;  // 32

    // prologue: fill stages 0..2
#pragma unroll
    for (int s = 0; s < 3; s++) {
        g1_load(sm1 + s * G1_STG, gA, gB1, gB3, s * 64, lrow, lch);
        CP_COMMIT();
    }

    for (int kt = 0; kt < KT; kt++) {
        CP_WAIT(2);
        __syncthreads();
        const int nx = kt + 3;
        if (nx < KT)
            g1_load(sm1 + (nx & 3) * G1_STG, gA, gB1, gB3, nx * 64, lrow, lch);
        CP_COMMIT();
        const __half* stb = sm1 + (kt & 3) * G1_STG;
        mma_stage_dual(stb, stb + 8192, stb + 16384, lane, wm, wn, acc1, acc3);
    }

    // epilogue: g = silu(s1*h1) * (s3*h3), fp16 store
    const float s1 = g_scale[0], s3v = g_scale[1];
    const int rb = bm * 128 + wm * 64;
    const int cb = bn * 128 + wn * 32;
#pragma unroll
    for (int mi = 0; mi < 4; mi++) {
        int r0 = rb + mi * 16 + (lane >> 2);
#pragma unroll
        for (int ni = 0; ni < 4; ni++) {
            int c = cb + ni * 8 + ((lane & 3) << 1);
            float h10 = s1 * acc1[mi][ni][0], h11 = s1 * acc1[mi][ni][1];
            float h12 = s1 * acc1[mi][ni][2], h13 = s1 * acc1[mi][ni][3];
            float h30 = s3v * acc3[mi][ni][0], h31 = s3v * acc3[mi][ni][1];
            float h32 = s3v * acc3[mi][ni][2], h33 = s3v * acc3[mi][ni][3];
            float g0 = siluf(h10) * h30, g1 = siluf(h11) * h31;
            float g2 = siluf(h12) * h32, g3 = siluf(h13) * h33;
            *(__half2*)(g_act + (size_t)r0 * HPAD + c)       = __floats2half2_rn(g0, g1);
            *(__half2*)(g_act + (size_t)(r0 + 8) * HPAD + c) = __floats2half2_rn(g2, g3);
        }
    }
}

// ---------------- GEMM2: out = s2 * (g . w2q^T) ----------------
// C tile 128x128, K=HPAD, BK=64, 4-stage pipeline (128KB dynamic smem).
#define G2_STG 16384   // halves per stage: A 8192 + B 8192
#define G2_SMEM (4 * G2_STG * 2)

__device__ __forceinline__ void g2_load(__half* st, const __half* gA, const __half* gB,
                                        int k0, int lrow, int lch) {
#pragma unroll
    for (int i = 0; i < 4; i++) {
        int row = lrow + (i << 5);
        int so = swz(row, lch);
        size_t go = (size_t)row * HPAD + k0 + lch * 8;
        CP_ASYNC16(sptr(st + so),        gA + go);
        CP_ASYNC16(sptr(st + 8192 + so), gB + go);
    }
}

__global__ __launch_bounds__(256, 1) void gemm2_k(float* __restrict__ out) {
    extern __shared__ __align__(16) __half sm2[];

    const int tid = threadIdx.x, lane = tid & 31, w = tid >> 5;
    const int wm = w >> 2, wn = w & 3;
    const int bm = blockIdx.y, bn = blockIdx.x;
    const int lrow = tid >> 3, lch = tid & 7;

    const __half* gA = g_act + (size_t)bm * 128 * HPAD;
    const __half* gB = g_w2q + (size_t)bn * 128 * HPAD;

    float acc[4][4][4];
#pragma unroll
    for (int i = 0; i < 4; i++)
#pragma unroll
        for (int j = 0; j < 4; j++)
#pragma unroll
            for (int k = 0; k < 4; k++) acc[i][j][k] = 0.f;

    const int KT = HPAD / 64;  // 86

#pragma unroll
    for (int s = 0; s < 3; s++) {
        g2_load(sm2 + s * G2_STG, gA, gB, s * 64, lrow, lch);
        CP_COMMIT();
    }

    for (int kt = 0; kt < KT; kt++) {
        CP_WAIT(2);
        __syncthreads();
        const int nx = kt + 3;
        if (nx < KT)
            g2_load(sm2 + (nx & 3) * G2_STG, gA, gB, nx * 64, lrow, lch);
        CP_COMMIT();
        const __half* stb = sm2 + (kt & 3) * G2_STG;
        mma_stage_single(stb, stb + 8192, lane, wm, wn, acc);
    }

    const float s2 = g_scale[2];
    const int rb = bm * 128 + wm * 64;
    const int cb = bn * 128 + wn * 32;
#pragma unroll
    for (int mi = 0; mi < 4; mi++) {
        int r0 = rb + mi * 16 + (lane >> 2);
#pragma unroll
        for (int ni = 0; ni < 4; ni++) {
            int c = cb + ni * 8 + ((lane & 3) << 1);
            float2 v;
            v.x = s2 * acc[mi][ni][0]; v.y = s2 * acc[mi][ni][1];
            *(float2*)(out + (size_t)r0 * DM + c) = v;
            v.x = s2 * acc[mi][ni][2]; v.y = s2 * acc[mi][ni][3];
            *(float2*)(out + (size_t)(r0 + 8) * DM + c) = v;
        }
    }
}

// ---------------- launch ----------------
extern "C" void kernel_launch(void* const* d_in, const int* in_sizes, int n_in,
                              void* d_out, int out_size) {
    const float* x  = (const float*)d_in[0];
    const float* w1 = (const float*)d_in[1];
    const float* w3 = (const float*)d_in[2];
    const float* w2 = (const float*)d_in[3];
    float* out = (float*)d_out;

    const int nw = HID * DM;  // 11,184,128

    cudaFuncSetAttribute(gemm1_k, cudaFuncAttributeMaxDynamicSharedMemorySize, G1_SMEM);
    cudaFuncSetAttribute(gemm2_k, cudaFuncAttributeMaxDynamicSharedMemorySize, G2_SMEM);

    // launch order keeps gemm1 as the 6th launch so ncu (-s 5 -c 1) profiles it
    reduce_abs3_k<<<dim3(512, 3), 256>>>(w1, w3, w2, nw);   // 1
    finalize3_k<<<3, 512>>>(nw);                            // 2
    quant_w13_k<<<dim3((HPAD * DM + 255) / 256, 2), 256>>>(w1, w3);  // 3
    quant_w2_k <<<(DM * HPAD + 255) / 256, 256>>>(w2);      // 4
    conv_x_k<<<(MTOT * DM / 4 + 255) / 256, 256>>>(x);      // 5
    gemm1_k<<<dim3(HPAD / 128, MTOT / 128), 256, G1_SMEM>>>();       // 6 <- profiled
    gemm2_k<<<dim3(DM / 128, MTOT / 128), 256, G2_SMEM>>>(out);      // 7
}